// round 14
// baseline (speedup 1.0000x reference)
#include <cuda_runtime.h>
#include <cstdint>

// ---------------- scratch (device globals; no allocs allowed) ----------------
// g_w16: h as fp16x2, fragment-major swizzled tiles of 64 jp-rows x 64 words:
//   T = jp>>6, r = jp&63, kk = r>>3, half = (r>>2)&1, lane2 = 4*(fp>>3)+(r&3),
//   slot = (2*lane2 + ((fp>>2)&1)) ^ ((lane2>>2)&1), cc = fp&3
__device__ uint32_t g_w16[4096 * 64];
__device__ float2   g_e1f1[8192];           // {exp(s1), exp(0.2*s1)}
__device__ float2   g_e2f2[8192];           // {exp(s2), exp(0.2*s2)}
__device__ float    g_part[8 * 8192 * 64];  // partial D per j-chunk (TRUE f order)
__device__ float    g_lpart[8 * 8192];      // partial softmax denom per j-chunk

// ---------------- helpers ----------------
__device__ __forceinline__ uint32_t smem_u32(const void* p) {
    uint32_t a;
    asm("{ .reg .u64 t; cvta.to.shared.u64 t, %1; cvt.u32.u64 %0, t; }" : "=r"(a) : "l"(p));
    return a;
}
__device__ __forceinline__ void cp_async16(uint32_t saddr, const void* gaddr) {
    asm volatile("cp.async.cg.shared.global [%0], [%1], 16;" :: "r"(saddr), "l"(gaddr) : "memory");
}
#define CP_COMMIT() asm volatile("cp.async.commit_group;" ::: "memory")
#define CP_WAIT(n)  asm volatile("cp.async.wait_group %0;" :: "n"(n) : "memory")

__device__ __forceinline__ void mma_f16(float* c, uint32_t a0, uint32_t a1, uint32_t a2,
                                        uint32_t a3, uint32_t b0, uint32_t b1) {
    asm volatile(
        "mma.sync.aligned.m16n8k16.row.col.f32.f16.f16.f32 "
        "{%0,%1,%2,%3}, {%4,%5,%6,%7}, {%8,%9}, {%0,%1,%2,%3};"
        : "+f"(c[0]), "+f"(c[1]), "+f"(c[2]), "+f"(c[3])
        : "r"(a0), "r"(a1), "r"(a2), "r"(a3), "r"(b0), "r"(b1));
}
__device__ __forceinline__ uint4 lds128(uint32_t addr) {
    uint4 v;
    asm volatile("ld.shared.v4.b32 {%0,%1,%2,%3}, [%4];"
                 : "=r"(v.x), "=r"(v.y), "=r"(v.z), "=r"(v.w) : "r"(addr));
    return v;
}
__device__ __forceinline__ float4 lds128f(uint32_t addr) {
    float4 v;
    asm volatile("ld.shared.v4.f32 {%0,%1,%2,%3}, [%4];"
                 : "=f"(v.x), "=f"(v.y), "=f"(v.z), "=f"(v.w) : "r"(addr));
    return v;
}
__device__ __forceinline__ uint2 lds64u(uint32_t addr) {
    uint2 v;
    asm volatile("ld.shared.v2.b32 {%0,%1}, [%2];" : "=r"(v.x), "=r"(v.y) : "r"(addr));
    return v;
}
// select v if bit (31-sh) of m is set
__device__ __forceinline__ float msel(uint32_t m, int sh, float v) {
    float r;
    asm("{ .reg .b32 t; shl.b32 t, %1, %2; slct.f32.s32 %0, 0f00000000, %3, t; }"
        : "=f"(r) : "r"(m), "r"(sh), "f"(v));
    return r;
}
__device__ __forceinline__ uint32_t pack16(float hi, float lo) {
    uint32_t d;
    asm("cvt.rn.f16x2.f32 %0, %1, %2;" : "=r"(d) : "f"(hi), "f"(lo));
    return d;
}
__device__ __forceinline__ void bstore(int4 m, uint32_t addr, int lane) {
    const uint32_t b0 = __ballot_sync(0xFFFFFFFFu, m.x != 0);
    const uint32_t b1 = __ballot_sync(0xFFFFFFFFu, m.y != 0);
    const uint32_t b2 = __ballot_sync(0xFFFFFFFFu, m.z != 0);
    const uint32_t b3 = __ballot_sync(0xFFFFFFFFu, m.w != 0);
    if (lane == 0)
        asm volatile("st.shared.v4.b32 [%0], {%1,%2,%3,%4};"
                     :: "r"(addr), "r"(b0), "r"(b1), "r"(b2), "r"(b3) : "memory");
}

// ============================================================================
// K1: h = input@W. W stays in L1 (64KB, shared across CTAs, __ldg LDG.128);
// only input staged in smem (32KB). 256 thr / 32 rows / grid 256 -> 6 CTA/SM,
// 48 warps/SM: latency hidden. 4f x 2r register blocking per thread.
// ============================================================================
static constexpr uint32_t PREP_SMEM = 32 * 1024;

__global__ void __launch_bounds__(256)
gat_prep(const float* __restrict__ inp, const float* __restrict__ W,
         const float* __restrict__ a)
{
    extern __shared__ float in_s[];         // 32*256 floats
    const int tid  = threadIdx.x;
    const int fq   = tid & 15;              // f-quad index (f = 4fq..4fq+3)
    const int rr   = tid >> 4;              // 0..15 -> rows base+2rr, base+2rr+1
    const int base = blockIdx.x * 32;

    // stage input rows (2048 float4, coalesced)
#pragma unroll
    for (int v = 0; v < 8; v++)
        reinterpret_cast<float4*>(in_s)[tid + v * 256] =
            reinterpret_cast<const float4*>(inp)[(size_t)base * 64 + tid + v * 256];
    __syncthreads();

    const float* inr0 = in_s + 2 * rr * 256;
    const float* inr1 = inr0 + 256;
    float aA[4] = {0.f, 0.f, 0.f, 0.f};     // row base+2rr
    float aB[4] = {0.f, 0.f, 0.f, 0.f};     // row base+2rr+1
#pragma unroll 8
    for (int k = 0; k < 256; k++) {
        const float4 w4 = __ldg(reinterpret_cast<const float4*>(&W[k * 64 + 4 * fq]));
        const float i0 = inr0[k];
        const float i1 = inr1[k];
        aA[0] += i0 * w4.x; aA[1] += i0 * w4.y; aA[2] += i0 * w4.z; aA[3] += i0 * w4.w;
        aB[0] += i1 * w4.x; aB[1] += i1 * w4.y; aB[2] += i1 * w4.z; aB[3] += i1 * w4.w;
    }

    // fp16 pair store (swizzled, fragment-major); jp pair = rows 2rr, 2rr+1
    {
        const int jp = (base >> 1) + rr;
        const int T  = jp >> 6, r = jp & 63;
        const size_t tb = (size_t)T * 4096 + (r >> 3) * 512 + ((r >> 2) & 1) * 256;
#pragma unroll
        for (int q = 0; q < 4; q++) {
            const int f  = 4 * fq + q;
            const int fp = (f & 7) * 8 + (f >> 3);
            const int lane2 = 4 * (fp >> 3) + (r & 3);
            const int slot  = (2 * lane2 + ((fp >> 2) & 1)) ^ ((lane2 >> 2) & 1);
            g_w16[tb + slot * 4 + (fp & 3)] = pack16(aB[q], aA[q]);
        }
    }

    // s1/s2: dot over this lane's 4 f's, reduce across the 16 fq-lanes
    const float4 a1q = __ldg(reinterpret_cast<const float4*>(&a[4 * fq]));
    const float4 a2q = __ldg(reinterpret_cast<const float4*>(&a[64 + 4 * fq]));
    float s1A = aA[0] * a1q.x + aA[1] * a1q.y + aA[2] * a1q.z + aA[3] * a1q.w;
    float s2A = aA[0] * a2q.x + aA[1] * a2q.y + aA[2] * a2q.z + aA[3] * a2q.w;
    float s1B = aB[0] * a1q.x + aB[1] * a1q.y + aB[2] * a1q.z + aB[3] * a1q.w;
    float s2B = aB[0] * a2q.x + aB[1] * a2q.y + aB[2] * a2q.z + aB[3] * a2q.w;
#pragma unroll
    for (int o = 8; o > 0; o >>= 1) {
        s1A += __shfl_xor_sync(0xFFFFFFFFu, s1A, o);
        s2A += __shfl_xor_sync(0xFFFFFFFFu, s2A, o);
        s1B += __shfl_xor_sync(0xFFFFFFFFu, s1B, o);
        s2B += __shfl_xor_sync(0xFFFFFFFFu, s2B, o);
    }
    if (fq == 0) {
        const int row = base + 2 * rr;
        g_e1f1[row]     = make_float2(expf(s1A), expf(0.2f * s1A));
        g_e2f2[row]     = make_float2(expf(s2A), expf(0.2f * s2A));
        g_e1f1[row + 1] = make_float2(expf(s1B), expf(0.2f * s1B));
        g_e2f2[row + 1] = make_float2(expf(s2B), expf(0.2f * s2B));
    }
}

// ============================================================================
// K2: fused adj-pack + masked attention + (P @ h) via mma.sync fp16 k16.
// Exact R11 configuration (best measured: 84.4us): grid 512 = 64 i-tiles x
// 8 j-chunks, 256 thr, 2 CTA/SM; 3-pair ballot rotation; f32 lacc.
// ============================================================================
static constexpr uint32_t SM_E2F2 = 0;                   // 8192 B
static constexpr uint32_t SM_MASK = 8192;                // 2 x 2048 B
static constexpr uint32_t SM_H0   = 12288;               // 16384 B
static constexpr uint32_t SM_H1   = SM_H0 + 16384;       // 28672
static constexpr uint32_t SMEM_TOTAL = SM_H1 + 16384;    // 45056 B

__global__ void __launch_bounds__(256, 2)
gat_attn(const int* __restrict__ adj)
{
    extern __shared__ char smem[];
    const uint32_t sb = smem_u32(smem);
    const int tid  = threadIdx.x;
    const int w    = tid >> 5;
    const int lane = tid & 31;
    const int g    = lane >> 2;
    const int ctg  = lane & 3;
    const int it   = blockIdx.x >> 3;
    const int jq   = blockIdx.x & 7;
    const int ibase = it * 128;
    const int jbase = jq * 1024;
    const int rbase = ibase + w * 16;

    // ---- preload E2F2 slice (1024 float2 = 512 float4)
    {
        const float4* src = reinterpret_cast<const float4*>(&g_e2f2[jbase]);
        float4* dst = reinterpret_cast<float4*>(smem + SM_E2F2);
        dst[tid]       = src[tid];
        dst[tid + 256] = src[tid + 256];
    }

    // ---- preload h tile 0 (linear 16KB) via cp.async
    {
        const uint32_t* src = &g_w16[(size_t)(jq * 8) * 4096];
#pragma unroll
        for (int v = 0; v < 4; v++) {
            const int id = tid + v * 256;
            cp_async16(sb + SM_H0 + id * 16, src + id * 4);
        }
        CP_COMMIT();
    }

    // ---- pack adj tile 0 masks (prologue)
    const int4* adjv = reinterpret_cast<const int4*>(adj);
    {
        const int4* psrc = adjv + (size_t)rbase * 2048 + (jbase >> 2);
        const uint32_t mdst = sb + SM_MASK + (uint32_t)w * 256;
#pragma unroll 4
        for (int r = 0; r < 16; r++)
            bstore(psrc[(size_t)r * 2048 + lane], mdst + r * 16, lane);
    }

    const float2 ef0 = g_e1f1[rbase + g];
    const float2 ef1 = g_e1f1[rbase + g + 8];
    const int o = ctg >> 1;
    const uint32_t lsw0 = ((uint32_t)lane * 32) ^ ((uint32_t)(lane & 4) << 2);

    float C[8][4];
#pragma unroll
    for (int n = 0; n < 8; n++)
#pragma unroll
        for (int q = 0; q < 4; q++) C[n][q] = 0.f;
    float lacc0 = 0.f, lacc1 = 0.f;

    for (int t = 0; t < 8; t++) {
        CP_WAIT(0);
        __syncthreads();

        const uint32_t hb = sb + ((t & 1) ? SM_H1 : SM_H0);

        // mask regs for tile t (pre-shift by o); rows g, g+8
        uint32_t mA0, mB0, mA1, mB1;
        {
            const uint32_t mb = sb + SM_MASK + (uint32_t)(t & 1) * 2048
                              + (uint32_t)w * 256 + (uint32_t)(ctg & 1) * 8;
            uint2 q0 = lds64u(mb + g * 16);
            uint2 q1 = lds64u(mb + (g + 8) * 16);
            mA0 = q0.x >> o; mB0 = q0.y >> o;
            mA1 = q1.x >> o; mB1 = q1.y >> o;
        }

        // issue h prefetch for t+1
        if (t < 7) {
            const uint32_t hn = sb + ((t & 1) ? SM_H0 : SM_H1);
            const uint32_t* src = &g_w16[(size_t)(jq * 8 + t + 1) * 4096];
#pragma unroll
            for (int v = 0; v < 4; v++) {
                const int id = tid + v * 256;
                cp_async16(hn + id * 16, src + id * 4);
            }
        }
        CP_COMMIT();

        // pack pipeline for tile t+1: 3-pair rotation, >=1.5-kstep load->ballot gap
        const int4* psrc = adjv + (size_t)rbase * 2048 + ((jbase + (t + 1) * 128) >> 2);
        const uint32_t mdst = sb + SM_MASK + (uint32_t)((t + 1) & 1) * 2048
                            + (uint32_t)w * 256;
        int4 pA0, pA1, pB0, pB1, pC0, pC1;
        if (t < 7) {
            pA0 = psrc[lane];            pA1 = psrc[2048 + lane];
            pB0 = psrc[2 * 2048 + lane]; pB1 = psrc[3 * 2048 + lane];
        }

#pragma unroll
        for (int kk = 0; kk < 8; kk++) {
            const int jc = t * 128 + kk * 16;

            const float4 c4 = lds128f(sb + SM_E2F2 + (jc + 2 * ctg) * 8);
            const float4 c8 = lds128f(sb + SM_E2F2 + (jc + 2 * ctg + 8) * 8);

            // P = adj ? max(E1*E2, F1*F2) : 0
            const float vL0 = fmaxf(ef0.x * c4.x, ef0.y * c4.y);
            const float vM0 = fmaxf(ef0.x * c4.z, ef0.y * c4.w);
            const float vH0 = fmaxf(ef0.x * c8.x, ef0.y * c8.y);
            const float vN0 = fmaxf(ef0.x * c8.z, ef0.y * c8.w);
            const float vL1 = fmaxf(ef1.x * c4.x, ef1.y * c4.y);
            const float vM1 = fmaxf(ef1.x * c4.z, ef1.y * c4.w);
            const float vH1 = fmaxf(ef1.x * c8.x, ef1.y * c8.y);
            const float vN1 = fmaxf(ef1.x * c8.z, ef1.y * c8.w);

            const float sL0 = msel(mA0, 31, vL0), sM0 = msel(mB0, 31, vM0);
            const float sH0 = msel(mA0, 29, vH0), sN0 = msel(mB0, 29, vN0);
            const float sL1 = msel(mA1, 31, vL1), sM1 = msel(mB1, 31, vM1);
            const float sH1 = msel(mA1, 29, vH1), sN1 = msel(mB1, 29, vN1);
            mA0 >>= 4; mB0 >>= 4; mA1 >>= 4; mB1 >>= 4;

            lacc0 += (sL0 + sM0) + (sH0 + sN0);
            lacc1 += (sL1 + sM1) + (sH1 + sN1);

            const uint32_t a0 = pack16(sM0, sL0);
            const uint32_t a1 = pack16(sM1, sL1);
            const uint32_t a2 = pack16(sN0, sH0);
            const uint32_t a3 = pack16(sN1, sH1);

            // B fragments: conflict-free swizzled chunks
            const uint32_t bbase = hb + (uint32_t)kk * 2048;
            const uint4 bl0 = lds128(bbase + lsw0);
            const uint4 bl1 = lds128(bbase + (lsw0 ^ 16));
            const uint4 bh0 = lds128(bbase + 1024 + lsw0);
            const uint4 bh1 = lds128(bbase + 1024 + (lsw0 ^ 16));

            mma_f16(C[0], a0, a1, a2, a3, bl0.x, bh0.x);
            mma_f16(C[1], a0, a1, a2, a3, bl0.y, bh0.y);
            mma_f16(C[2], a0, a1, a2, a3, bl0.z, bh0.z);
            mma_f16(C[3], a0, a1, a2, a3, bl0.w, bh0.w);
            mma_f16(C[4], a0, a1, a2, a3, bl1.x, bh1.x);
            mma_f16(C[5], a0, a1, a2, a3, bl1.y, bh1.y);
            mma_f16(C[6], a0, a1, a2, a3, bl1.z, bh1.z);
            mma_f16(C[7], a0, a1, a2, a3, bl1.w, bh1.w);

            // ballot schedule (rows of tile t+1); loads >=1.5 ksteps ahead of use
            if (t < 7) {
                if (kk == 0) {
                    pC0 = psrc[4 * 2048 + lane]; pC1 = psrc[5 * 2048 + lane];
                } else if (kk == 1) {
                    bstore(pA0, mdst + 0 * 16, lane);  bstore(pA1, mdst + 1 * 16, lane);
                    pA0 = psrc[6 * 2048 + lane];  pA1 = psrc[7 * 2048 + lane];
                } else if (kk == 2) {
                    bstore(pB0, mdst + 2 * 16, lane);  bstore(pB1, mdst + 3 * 16, lane);
                    pB0 = psrc[8 * 2048 + lane];  pB1 = psrc[9 * 2048 + lane];
                } else if (kk == 3) {
                    bstore(pC0, mdst + 4 * 16, lane);  bstore(pC1, mdst + 5 * 16, lane);
                    pC0 = psrc[10 * 2048 + lane]; pC1 = psrc[11 * 2048 + lane];
                } else if (kk == 4) {
                    bstore(pA0, mdst + 6 * 16, lane);  bstore(pA1, mdst + 7 * 16, lane);
                    pA0 = psrc[12 * 2048 + lane]; pA1 = psrc[13 * 2048 + lane];
                } else if (kk == 5) {
                    bstore(pB0, mdst + 8 * 16, lane);  bstore(pB1, mdst + 9 * 16, lane);
                    pB0 = psrc[14 * 2048 + lane]; pB1 = psrc[15 * 2048 + lane];
                } else if (kk == 6) {
                    bstore(pC0, mdst + 10 * 16, lane); bstore(pC1, mdst + 11 * 16, lane);
                } else {
                    bstore(pA0, mdst + 12 * 16, lane); bstore(pA1, mdst + 13 * 16, lane);
                    bstore(pB0, mdst + 14 * 16, lane); bstore(pB1, mdst + 15 * 16, lane);
                }
            }
        }
    }

    // ---- l: reduce over the 4 ctg threads, write rows g, g+8
    lacc0 += __shfl_xor_sync(0xFFFFFFFFu, lacc0, 1);
    lacc0 += __shfl_xor_sync(0xFFFFFFFFu, lacc0, 2);
    lacc1 += __shfl_xor_sync(0xFFFFFFFFu, lacc1, 1);
    lacc1 += __shfl_xor_sync(0xFFFFFFFFu, lacc1, 2);
    if (ctg == 0) {
        float* lp = &g_lpart[(size_t)jq * 8192];
        lp[rbase + g]     = lacc0;
        lp[rbase + g + 8] = lacc1;
    }

    // ---- write D partials (TRUE f order): mma #nt covers f = nt*8 + mma-n
    float* d0 = &g_part[((size_t)jq * 8192 + rbase + g) * 64];
    float* d1 = d0 + 8 * 64;
#pragma unroll
    for (int nt = 0; nt < 8; nt++) {
        const int col = nt * 8 + 2 * ctg;
        *reinterpret_cast<float2*>(&d0[col]) = make_float2(C[nt][0], C[nt][1]);
        *reinterpret_cast<float2*>(&d1[col]) = make_float2(C[nt][2], C[nt][3]);
    }
}

// ============================================================================
// K3: combine 8 partials, normalize, elu.
// ============================================================================
__device__ __forceinline__ float eluf(float x) { return x > 0.f ? x : expm1f(x); }

__global__ void __launch_bounds__(256)
gat_final(float* __restrict__ out)
{
    const int gi = blockIdx.x * 256 + threadIdx.x;
    const int i  = gi >> 4;
    const int c0 = (gi & 15) * 4;
    float4 acc = *reinterpret_cast<const float4*>(&g_part[(size_t)i * 64 + c0]);
    float l = g_lpart[i];
#pragma unroll
    for (int q = 1; q < 8; q++) {
        const float4 d = *reinterpret_cast<const float4*>(
            &g_part[((size_t)q * 8192 + i) * 64 + c0]);
        acc.x += d.x; acc.y += d.y; acc.z += d.z; acc.w += d.w;
        l += g_lpart[(size_t)q * 8192 + i];
    }
    const float inv = 1.0f / l;
    float4 o;
    o.x = eluf(acc.x * inv);
    o.y = eluf(acc.y * inv);
    o.z = eluf(acc.z * inv);
    o.w = eluf(acc.w * inv);
    *reinterpret_cast<float4*>(&out[(size_t)i * 64 + c0]) = o;
}

// ============================================================================
extern "C" void kernel_launch(void* const* d_in, const int* in_sizes, int n_in,
                              void* d_out, int out_size)
{
    const float* inp = (const float*)d_in[0];
    const int*   adj = (const int*)d_in[1];
    const float* W   = (const float*)d_in[2];
    const float* a   = (const float*)d_in[3];
    float* out = (float*)d_out;

    cudaFuncSetAttribute((const void*)gat_attn,
                         cudaFuncAttributeMaxDynamicSharedMemorySize, SMEM_TOTAL);

    gat_prep<<<256, 256, PREP_SMEM>>>(inp, W, a);
    gat_attn<<<512, 256, SMEM_TOTAL>>>(adj);
    gat_final<<<512, 256>>>(out);
}

// round 15
// speedup vs baseline: 1.2157x; 1.2157x over previous
#include <cuda_runtime.h>
#include <cstdint>

// ---------------- scratch (device globals; no allocs allowed) ----------------
// g_w16: h as fp16x2, fragment-major swizzled tiles of 64 jp-rows x 64 words:
//   T = jp>>6, r = jp&63, kk = r>>3, half = (r>>2)&1, lane2 = 4*(fp>>3)+(r&3),
//   slot = (2*lane2 + ((fp>>2)&1)) ^ ((lane2>>2)&1), cc = fp&3
__device__ uint32_t g_w16[4096 * 64];
__device__ float2   g_e1f1[8192];           // {exp(s1), exp(0.2*s1)}
__device__ float2   g_e2f2[8192];           // {exp(s2), exp(0.2*s2)}
__device__ float    g_part[8 * 8192 * 64];  // partial D per j-chunk (TRUE f order)
__device__ float    g_lpart[8 * 8192];      // partial softmax denom per j-chunk

// ---------------- helpers ----------------
__device__ __forceinline__ uint32_t smem_u32(const void* p) {
    uint32_t a;
    asm("{ .reg .u64 t; cvta.to.shared.u64 t, %1; cvt.u32.u64 %0, t; }" : "=r"(a) : "l"(p));
    return a;
}
__device__ __forceinline__ void cp_async16(uint32_t saddr, const void* gaddr) {
    asm volatile("cp.async.cg.shared.global [%0], [%1], 16;" :: "r"(saddr), "l"(gaddr) : "memory");
}
#define CP_COMMIT() asm volatile("cp.async.commit_group;" ::: "memory")
#define CP_WAIT(n)  asm volatile("cp.async.wait_group %0;" :: "n"(n) : "memory")

__device__ __forceinline__ void mma_f16(float* c, uint32_t a0, uint32_t a1, uint32_t a2,
                                        uint32_t a3, uint32_t b0, uint32_t b1) {
    asm volatile(
        "mma.sync.aligned.m16n8k16.row.col.f32.f16.f16.f32 "
        "{%0,%1,%2,%3}, {%4,%5,%6,%7}, {%8,%9}, {%0,%1,%2,%3};"
        : "+f"(c[0]), "+f"(c[1]), "+f"(c[2]), "+f"(c[3])
        : "r"(a0), "r"(a1), "r"(a2), "r"(a3), "r"(b0), "r"(b1));
}
__device__ __forceinline__ uint4 lds128(uint32_t addr) {
    uint4 v;
    asm volatile("ld.shared.v4.b32 {%0,%1,%2,%3}, [%4];"
                 : "=r"(v.x), "=r"(v.y), "=r"(v.z), "=r"(v.w) : "r"(addr));
    return v;
}
__device__ __forceinline__ float4 lds128f(uint32_t addr) {
    float4 v;
    asm volatile("ld.shared.v4.f32 {%0,%1,%2,%3}, [%4];"
                 : "=f"(v.x), "=f"(v.y), "=f"(v.z), "=f"(v.w) : "r"(addr));
    return v;
}
__device__ __forceinline__ uint2 lds64u(uint32_t addr) {
    uint2 v;
    asm volatile("ld.shared.v2.b32 {%0,%1}, [%2];" : "=r"(v.x), "=r"(v.y) : "r"(addr));
    return v;
}
// select v if bit (31-sh) of m is set
__device__ __forceinline__ float msel(uint32_t m, int sh, float v) {
    float r;
    asm("{ .reg .b32 t; shl.b32 t, %1, %2; slct.f32.s32 %0, 0f00000000, %3, t; }"
        : "=f"(r) : "r"(m), "r"(sh), "f"(v));
    return r;
}
__device__ __forceinline__ uint32_t pack16(float hi, float lo) {
    uint32_t d;
    asm("cvt.rn.f16x2.f32 %0, %1, %2;" : "=r"(d) : "f"(hi), "f"(lo));
    return d;
}
__device__ __forceinline__ void bstore(int4 m, uint32_t addr, int lane) {
    const uint32_t b0 = __ballot_sync(0xFFFFFFFFu, m.x != 0);
    const uint32_t b1 = __ballot_sync(0xFFFFFFFFu, m.y != 0);
    const uint32_t b2 = __ballot_sync(0xFFFFFFFFu, m.z != 0);
    const uint32_t b3 = __ballot_sync(0xFFFFFFFFu, m.w != 0);
    if (lane == 0)
        asm volatile("st.shared.v4.b32 [%0], {%1,%2,%3,%4};"
                     :: "r"(addr), "r"(b0), "r"(b1), "r"(b2), "r"(b3) : "memory");
}

// ============================================================================
// K1: h = input@W. W staged in smem (64KB) + input (32KB) = 96KB -> 2 CTA/SM.
// grid 256 x 256 thr = one full wave over 148 SMs. 4f x 2r register blocking:
// fq = tid&15 (f-quad), rr = tid>>4 (row pair 2rr, 2rr+1); block = 32 rows.
// ============================================================================
static constexpr uint32_t PREP_SMEM = 64 * 1024 + 32 * 1024;

__global__ void __launch_bounds__(256)
gat_prep(const float* __restrict__ inp, const float* __restrict__ W,
         const float* __restrict__ a)
{
    extern __shared__ float dsm[];
    float* W_s  = dsm;          // 16384 floats
    float* in_s = dsm + 16384;  // 32*256 floats
    const int tid  = threadIdx.x;
    const int fq   = tid & 15;              // f-quad index (f = 4fq..4fq+3)
    const int rr   = tid >> 4;              // 0..15 -> rows base+2rr, base+2rr+1
    const int base = blockIdx.x * 32;

    // stage W (4096 float4) + input rows (2048 float4), coalesced
#pragma unroll
    for (int v = 0; v < 16; v++)
        reinterpret_cast<float4*>(W_s)[tid + v * 256] =
            reinterpret_cast<const float4*>(W)[tid + v * 256];
#pragma unroll
    for (int v = 0; v < 8; v++)
        reinterpret_cast<float4*>(in_s)[tid + v * 256] =
            reinterpret_cast<const float4*>(inp)[(size_t)base * 64 + tid + v * 256];
    __syncthreads();

    const float* inr0 = in_s + 2 * rr * 256;
    const float* inr1 = inr0 + 256;
    float aA[4] = {0.f, 0.f, 0.f, 0.f};     // row base+2rr
    float aB[4] = {0.f, 0.f, 0.f, 0.f};     // row base+2rr+1
#pragma unroll 8
    for (int k = 0; k < 256; k++) {
        const float4 w4 = *reinterpret_cast<const float4*>(&W_s[k * 64 + 4 * fq]);
        const float i0 = inr0[k];
        const float i1 = inr1[k];
        aA[0] += i0 * w4.x; aA[1] += i0 * w4.y; aA[2] += i0 * w4.z; aA[3] += i0 * w4.w;
        aB[0] += i1 * w4.x; aB[1] += i1 * w4.y; aB[2] += i1 * w4.z; aB[3] += i1 * w4.w;
    }

    // fp16 pair store (swizzled, fragment-major); jp pair = rows 2rr, 2rr+1
    {
        const int jp = (base >> 1) + rr;
        const int T  = jp >> 6, r = jp & 63;
        const size_t tb = (size_t)T * 4096 + (r >> 3) * 512 + ((r >> 2) & 1) * 256;
#pragma unroll
        for (int q = 0; q < 4; q++) {
            const int f  = 4 * fq + q;
            const int fp = (f & 7) * 8 + (f >> 3);
            const int lane2 = 4 * (fp >> 3) + (r & 3);
            const int slot  = (2 * lane2 + ((fp >> 2) & 1)) ^ ((lane2 >> 2) & 1);
            g_w16[tb + slot * 4 + (fp & 3)] = pack16(aB[q], aA[q]);
        }
    }

    // s1/s2: dot over this lane's 4 f's, reduce across the 16 fq-lanes
    const float4 a1q = __ldg(reinterpret_cast<const float4*>(&a[4 * fq]));
    const float4 a2q = __ldg(reinterpret_cast<const float4*>(&a[64 + 4 * fq]));
    float s1A = aA[0] * a1q.x + aA[1] * a1q.y + aA[2] * a1q.z + aA[3] * a1q.w;
    float s2A = aA[0] * a2q.x + aA[1] * a2q.y + aA[2] * a2q.z + aA[3] * a2q.w;
    float s1B = aB[0] * a1q.x + aB[1] * a1q.y + aB[2] * a1q.z + aB[3] * a1q.w;
    float s2B = aB[0] * a2q.x + aB[1] * a2q.y + aB[2] * a2q.z + aB[3] * a2q.w;
#pragma unroll
    for (int o = 8; o > 0; o >>= 1) {
        s1A += __shfl_xor_sync(0xFFFFFFFFu, s1A, o);
        s2A += __shfl_xor_sync(0xFFFFFFFFu, s2A, o);
        s1B += __shfl_xor_sync(0xFFFFFFFFu, s1B, o);
        s2B += __shfl_xor_sync(0xFFFFFFFFu, s2B, o);
    }
    if (fq == 0) {
        const int row = base + 2 * rr;
        g_e1f1[row]     = make_float2(expf(s1A), expf(0.2f * s1A));
        g_e2f2[row]     = make_float2(expf(s2A), expf(0.2f * s2A));
        g_e1f1[row + 1] = make_float2(expf(s1B), expf(0.2f * s1B));
        g_e2f2[row + 1] = make_float2(expf(s2B), expf(0.2f * s2B));
    }
}

// ============================================================================
// K2: fused adj-pack + masked attention + (P @ h) via mma.sync fp16 k16.
// Exact R11 configuration (best measured: 84.4us): grid 512 = 64 i-tiles x
// 8 j-chunks, 256 thr, 2 CTA/SM; 3-pair ballot rotation; f32 lacc.
// ============================================================================
static constexpr uint32_t SM_E2F2 = 0;                   // 8192 B
static constexpr uint32_t SM_MASK = 8192;                // 2 x 2048 B
static constexpr uint32_t SM_H0   = 12288;               // 16384 B
static constexpr uint32_t SM_H1   = SM_H0 + 16384;       // 28672
static constexpr uint32_t SMEM_TOTAL = SM_H1 + 16384;    // 45056 B

__global__ void __launch_bounds__(256, 2)
gat_attn(const int* __restrict__ adj)
{
    extern __shared__ char smem[];
    const uint32_t sb = smem_u32(smem);
    const int tid  = threadIdx.x;
    const int w    = tid >> 5;
    const int lane = tid & 31;
    const int g    = lane >> 2;
    const int ctg  = lane & 3;
    const int it   = blockIdx.x >> 3;
    const int jq   = blockIdx.x & 7;
    const int ibase = it * 128;
    const int jbase = jq * 1024;
    const int rbase = ibase + w * 16;

    // ---- preload E2F2 slice (1024 float2 = 512 float4)
    {
        const float4* src = reinterpret_cast<const float4*>(&g_e2f2[jbase]);
        float4* dst = reinterpret_cast<float4*>(smem + SM_E2F2);
        dst[tid]       = src[tid];
        dst[tid + 256] = src[tid + 256];
    }

    // ---- preload h tile 0 (linear 16KB) via cp.async
    {
        const uint32_t* src = &g_w16[(size_t)(jq * 8) * 4096];
#pragma unroll
        for (int v = 0; v < 4; v++) {
            const int id = tid + v * 256;
            cp_async16(sb + SM_H0 + id * 16, src + id * 4);
        }
        CP_COMMIT();
    }

    // ---- pack adj tile 0 masks (prologue)
    const int4* adjv = reinterpret_cast<const int4*>(adj);
    {
        const int4* psrc = adjv + (size_t)rbase * 2048 + (jbase >> 2);
        const uint32_t mdst = sb + SM_MASK + (uint32_t)w * 256;
#pragma unroll 4
        for (int r = 0; r < 16; r++)
            bstore(psrc[(size_t)r * 2048 + lane], mdst + r * 16, lane);
    }

    const float2 ef0 = g_e1f1[rbase + g];
    const float2 ef1 = g_e1f1[rbase + g + 8];
    const int o = ctg >> 1;
    const uint32_t lsw0 = ((uint32_t)lane * 32) ^ ((uint32_t)(lane & 4) << 2);

    float C[8][4];
#pragma unroll
    for (int n = 0; n < 8; n++)
#pragma unroll
        for (int q = 0; q < 4; q++) C[n][q] = 0.f;
    float lacc0 = 0.f, lacc1 = 0.f;

    for (int t = 0; t < 8; t++) {
        CP_WAIT(0);
        __syncthreads();

        const uint32_t hb = sb + ((t & 1) ? SM_H1 : SM_H0);

        // mask regs for tile t (pre-shift by o); rows g, g+8
        uint32_t mA0, mB0, mA1, mB1;
        {
            const uint32_t mb = sb + SM_MASK + (uint32_t)(t & 1) * 2048
                              + (uint32_t)w * 256 + (uint32_t)(ctg & 1) * 8;
            uint2 q0 = lds64u(mb + g * 16);
            uint2 q1 = lds64u(mb + (g + 8) * 16);
            mA0 = q0.x >> o; mB0 = q0.y >> o;
            mA1 = q1.x >> o; mB1 = q1.y >> o;
        }

        // issue h prefetch for t+1
        if (t < 7) {
            const uint32_t hn = sb + ((t & 1) ? SM_H0 : SM_H1);
            const uint32_t* src = &g_w16[(size_t)(jq * 8 + t + 1) * 4096];
#pragma unroll
            for (int v = 0; v < 4; v++) {
                const int id = tid + v * 256;
                cp_async16(hn + id * 16, src + id * 4);
            }
        }
        CP_COMMIT();

        // pack pipeline for tile t+1: 3-pair rotation, >=1.5-kstep load->ballot gap
        const int4* psrc = adjv + (size_t)rbase * 2048 + ((jbase + (t + 1) * 128) >> 2);
        const uint32_t mdst = sb + SM_MASK + (uint32_t)((t + 1) & 1) * 2048
                            + (uint32_t)w * 256;
        int4 pA0, pA1, pB0, pB1, pC0, pC1;
        if (t < 7) {
            pA0 = psrc[lane];            pA1 = psrc[2048 + lane];
            pB0 = psrc[2 * 2048 + lane]; pB1 = psrc[3 * 2048 + lane];
        }

#pragma unroll
        for (int kk = 0; kk < 8; kk++) {
            const int jc = t * 128 + kk * 16;

            const float4 c4 = lds128f(sb + SM_E2F2 + (jc + 2 * ctg) * 8);
            const float4 c8 = lds128f(sb + SM_E2F2 + (jc + 2 * ctg + 8) * 8);

            // P = adj ? max(E1*E2, F1*F2) : 0
            const float vL0 = fmaxf(ef0.x * c4.x, ef0.y * c4.y);
            const float vM0 = fmaxf(ef0.x * c4.z, ef0.y * c4.w);
            const float vH0 = fmaxf(ef0.x * c8.x, ef0.y * c8.y);
            const float vN0 = fmaxf(ef0.x * c8.z, ef0.y * c8.w);
            const float vL1 = fmaxf(ef1.x * c4.x, ef1.y * c4.y);
            const float vM1 = fmaxf(ef1.x * c4.z, ef1.y * c4.w);
            const float vH1 = fmaxf(ef1.x * c8.x, ef1.y * c8.y);
            const float vN1 = fmaxf(ef1.x * c8.z, ef1.y * c8.w);

            const float sL0 = msel(mA0, 31, vL0), sM0 = msel(mB0, 31, vM0);
            const float sH0 = msel(mA0, 29, vH0), sN0 = msel(mB0, 29, vN0);
            const float sL1 = msel(mA1, 31, vL1), sM1 = msel(mB1, 31, vM1);
            const float sH1 = msel(mA1, 29, vH1), sN1 = msel(mB1, 29, vN1);
            mA0 >>= 4; mB0 >>= 4; mA1 >>= 4; mB1 >>= 4;

            lacc0 += (sL0 + sM0) + (sH0 + sN0);
            lacc1 += (sL1 + sM1) + (sH1 + sN1);

            const uint32_t a0 = pack16(sM0, sL0);
            const uint32_t a1 = pack16(sM1, sL1);
            const uint32_t a2 = pack16(sN0, sH0);
            const uint32_t a3 = pack16(sN1, sH1);

            // B fragments: conflict-free swizzled chunks
            const uint32_t bbase = hb + (uint32_t)kk * 2048;
            const uint4 bl0 = lds128(bbase + lsw0);
            const uint4 bl1 = lds128(bbase + (lsw0 ^ 16));
            const uint4 bh0 = lds128(bbase + 1024 + lsw0);
            const uint4 bh1 = lds128(bbase + 1024 + (lsw0 ^ 16));

            mma_f16(C[0], a0, a1, a2, a3, bl0.x, bh0.x);
            mma_f16(C[1], a0, a1, a2, a3, bl0.y, bh0.y);
            mma_f16(C[2], a0, a1, a2, a3, bl0.z, bh0.z);
            mma_f16(C[3], a0, a1, a2, a3, bl0.w, bh0.w);
            mma_f16(C[4], a0, a1, a2, a3, bl1.x, bh1.x);
            mma_f16(C[5], a0, a1, a2, a3, bl1.y, bh1.y);
            mma_f16(C[6], a0, a1, a2, a3, bl1.z, bh1.z);
            mma_f16(C[7], a0, a1, a2, a3, bl1.w, bh1.w);

            // ballot schedule (rows of tile t+1); loads >=1.5 ksteps ahead of use
            if (t < 7) {
                if (kk == 0) {
                    pC0 = psrc[4 * 2048 + lane]; pC1 = psrc[5 * 2048 + lane];
                } else if (kk == 1) {
                    bstore(pA0, mdst + 0 * 16, lane);  bstore(pA1, mdst + 1 * 16, lane);
                    pA0 = psrc[6 * 2048 + lane];  pA1 = psrc[7 * 2048 + lane];
                } else if (kk == 2) {
                    bstore(pB0, mdst + 2 * 16, lane);  bstore(pB1, mdst + 3 * 16, lane);
                    pB0 = psrc[8 * 2048 + lane];  pB1 = psrc[9 * 2048 + lane];
                } else if (kk == 3) {
                    bstore(pC0, mdst + 4 * 16, lane);  bstore(pC1, mdst + 5 * 16, lane);
                    pC0 = psrc[10 * 2048 + lane]; pC1 = psrc[11 * 2048 + lane];
                } else if (kk == 4) {
                    bstore(pA0, mdst + 6 * 16, lane);  bstore(pA1, mdst + 7 * 16, lane);
                    pA0 = psrc[12 * 2048 + lane]; pA1 = psrc[13 * 2048 + lane];
                } else if (kk == 5) {
                    bstore(pB0, mdst + 8 * 16, lane);  bstore(pB1, mdst + 9 * 16, lane);
                    pB0 = psrc[14 * 2048 + lane]; pB1 = psrc[15 * 2048 + lane];
                } else if (kk == 6) {
                    bstore(pC0, mdst + 10 * 16, lane); bstore(pC1, mdst + 11 * 16, lane);
                } else {
                    bstore(pA0, mdst + 12 * 16, lane); bstore(pA1, mdst + 13 * 16, lane);
                    bstore(pB0, mdst + 14 * 16, lane); bstore(pB1, mdst + 15 * 16, lane);
                }
            }
        }
    }

    // ---- l: reduce over the 4 ctg threads, write rows g, g+8
    lacc0 += __shfl_xor_sync(0xFFFFFFFFu, lacc0, 1);
    lacc0 += __shfl_xor_sync(0xFFFFFFFFu, lacc0, 2);
    lacc1 += __shfl_xor_sync(0xFFFFFFFFu, lacc1, 1);
    lacc1 += __shfl_xor_sync(0xFFFFFFFFu, lacc1, 2);
    if (ctg == 0) {
        float* lp = &g_lpart[(size_t)jq * 8192];
        lp[rbase + g]     = lacc0;
        lp[rbase + g + 8] = lacc1;
    }

    // ---- write D partials (TRUE f order): mma #nt covers f = nt*8 + mma-n
    float* d0 = &g_part[((size_t)jq * 8192 + rbase + g) * 64];
    float* d1 = d0 + 8 * 64;
#pragma unroll
    for (int nt = 0; nt < 8; nt++) {
        const int col = nt * 8 + 2 * ctg;
        *reinterpret_cast<float2*>(&d0[col]) = make_float2(C[nt][0], C[nt][1]);
        *reinterpret_cast<float2*>(&d1[col]) = make_float2(C[nt][2], C[nt][3]);
    }
}

// ============================================================================
// K3: combine 8 partials, normalize, elu.
// ============================================================================
__device__ __forceinline__ float eluf(float x) { return x > 0.f ? x : expm1f(x); }

__global__ void __launch_bounds__(256)
gat_final(float* __restrict__ out)
{
    const int gi = blockIdx.x * 256 + threadIdx.x;
    const int i  = gi >> 4;
    const int c0 = (gi & 15) * 4;
    float4 acc = *reinterpret_cast<const float4*>(&g_part[(size_t)i * 64 + c0]);
    float l = g_lpart[i];
#pragma unroll
    for (int q = 1; q < 8; q++) {
        const float4 d = *reinterpret_cast<const float4*>(
            &g_part[((size_t)q * 8192 + i) * 64 + c0]);
        acc.x += d.x; acc.y += d.y; acc.z += d.z; acc.w += d.w;
        l += g_lpart[(size_t)q * 8192 + i];
    }
    const float inv = 1.0f / l;
    float4 o;
    o.x = eluf(acc.x * inv);
    o.y = eluf(acc.y * inv);
    o.z = eluf(acc.z * inv);
    o.w = eluf(acc.w * inv);
    *reinterpret_cast<float4*>(&out[(size_t)i * 64 + c0]) = o;
}

// ============================================================================
extern "C" void kernel_launch(void* const* d_in, const int* in_sizes, int n_in,
                              void* d_out, int out_size)
{
    const float* inp = (const float*)d_in[0];
    const int*   adj = (const int*)d_in[1];
    const float* W   = (const float*)d_in[2];
    const float* a   = (const float*)d_in[3];
    float* out = (float*)d_out;

    cudaFuncSetAttribute((const void*)gat_prep,
                         cudaFuncAttributeMaxDynamicSharedMemorySize, PREP_SMEM);
    cudaFuncSetAttribute((const void*)gat_attn,
                         cudaFuncAttributeMaxDynamicSharedMemorySize, SMEM_TOTAL);

    gat_prep<<<256, 256, PREP_SMEM>>>(inp, W, a);
    gat_attn<<<512, 256, SMEM_TOTAL>>>(adj);
    gat_final<<<512, 256>>>(out);
}